// round 1
// baseline (speedup 1.0000x reference)
#include <cuda_runtime.h>
#include <math.h>

// Problem constants
#define Bsz 4
#define Sq  2048
#define Dm  1024
#define Hn  16
#define DHd 64
#define Mrows (Bsz * Sq)          // 8192
#define QKVCOLS (3 * Dm)          // 3072

// Scratch (allocation-free rule: __device__ globals)
__device__ float g_qkv[(size_t)Mrows * QKVCOLS];   // [8192, 3072] : Q|K|V
__device__ float g_attn[(size_t)Mrows * Dm];       // [8192, 1024] merged heads

// ---------------------------------------------------------------------------
// GEMM: C[M,N] = A[M,K] @ W[K,N] + bias[N]
// 128x128x16 tile, 256 threads, 8x8 register blocking.
// ---------------------------------------------------------------------------
#define TM 128
#define TN 128
#define TK 16

__global__ __launch_bounds__(256)
void gemm_bias_kernel(const float* __restrict__ A,
                      const float* __restrict__ W,
                      const float* __restrict__ bias,
                      float* __restrict__ C,
                      int M, int N, int K)
{
    __shared__ float As[TK][TM + 4];   // transposed A tile, padded
    __shared__ float Ws[TK][TN];

    const int tid = threadIdx.x;
    const int tx = tid & 15;           // 0..15 -> 8 cols each
    const int ty = tid >> 4;           // 0..15 -> 8 rows each
    const int m0 = blockIdx.y * TM;
    const int n0 = blockIdx.x * TN;

    float acc[8][8];
#pragma unroll
    for (int i = 0; i < 8; ++i)
#pragma unroll
        for (int j = 0; j < 8; ++j) acc[i][j] = 0.f;

    for (int k0 = 0; k0 < K; k0 += TK) {
        // Load A tile: 128 rows x 16 cols = 512 float4 (2 per thread)
#pragma unroll
        for (int i = 0; i < 2; ++i) {
            int v   = tid + i * 256;        // 0..511
            int row = v >> 2;               // 4 float4 per row
            int c4  = (v & 3) * 4;
            float4 a4 = *(const float4*)&A[(size_t)(m0 + row) * K + k0 + c4];
            As[c4 + 0][row] = a4.x;
            As[c4 + 1][row] = a4.y;
            As[c4 + 2][row] = a4.z;
            As[c4 + 3][row] = a4.w;
        }
        // Load W tile: 16 rows x 128 cols = 512 float4 (2 per thread)
#pragma unroll
        for (int i = 0; i < 2; ++i) {
            int v   = tid + i * 256;
            int row = v >> 5;               // 32 float4 per row
            int c4  = (v & 31) * 4;
            *(float4*)&Ws[row][c4] =
                *(const float4*)&W[(size_t)(k0 + row) * N + n0 + c4];
        }
        __syncthreads();

#pragma unroll
        for (int kk = 0; kk < TK; ++kk) {
            float a[8], b[8];
            *(float4*)&a[0] = *(const float4*)&As[kk][ty * 8];
            *(float4*)&a[4] = *(const float4*)&As[kk][ty * 8 + 4];
            *(float4*)&b[0] = *(const float4*)&Ws[kk][tx * 8];
            *(float4*)&b[4] = *(const float4*)&Ws[kk][tx * 8 + 4];
#pragma unroll
            for (int i = 0; i < 8; ++i)
#pragma unroll
                for (int j = 0; j < 8; ++j)
                    acc[i][j] += a[i] * b[j];
        }
        __syncthreads();
    }

    // Epilogue: + bias, store
    float bv[8];
#pragma unroll
    for (int j = 0; j < 8; ++j) bv[j] = bias[n0 + tx * 8 + j];

#pragma unroll
    for (int i = 0; i < 8; ++i) {
        size_t row = (size_t)(m0 + ty * 8 + i);
        float* crow = &C[row * N + n0 + tx * 8];
        float4 o0, o1;
        o0.x = acc[i][0] + bv[0]; o0.y = acc[i][1] + bv[1];
        o0.z = acc[i][2] + bv[2]; o0.w = acc[i][3] + bv[3];
        o1.x = acc[i][4] + bv[4]; o1.y = acc[i][5] + bv[5];
        o1.z = acc[i][6] + bv[6]; o1.w = acc[i][7] + bv[7];
        *(float4*)&crow[0] = o0;
        *(float4*)&crow[4] = o1;
    }
}

// ---------------------------------------------------------------------------
// Flash attention (fp32, causal). One block per (b, h, 128-query-row tile).
// 128 threads; thread t owns query row qr0+t: q[64] and o[64] in registers.
// K/V staged as 32-key tiles in shared memory; broadcast LDS.128 reads.
// ---------------------------------------------------------------------------
#define QROWS 128
#define KT    32

__global__ __launch_bounds__(128)
void attn_kernel(const float* __restrict__ qkv, float* __restrict__ out)
{
    __shared__ float4 Ks[KT * 16];   // [32 keys][64 floats] as float4
    __shared__ float4 Vs[KT * 16];

    const int tid = threadIdx.x;
    const int h   = blockIdx.y;
    const int b   = blockIdx.z;
    const int qr0 = blockIdx.x * QROWS;
    const int qr  = qr0 + tid;

    const size_t rs = (size_t)QKVCOLS;   // 3072 floats per token row

    // Load this thread's query row into registers
    const float4* qrow =
        (const float4*)(qkv + (size_t)(b * Sq + qr) * rs + h * DHd);
    float4 q[16];
#pragma unroll
    for (int i = 0; i < 16; ++i) q[i] = qrow[i];

    float o[64];
#pragma unroll
    for (int i = 0; i < 64; ++i) o[i] = 0.f;
    float m = -1e30f, l = 0.f;

    const int ntiles = (qr0 >> 5) + 4;   // cover keys up to qr0+127 (causal)

    for (int t = 0; t < ntiles; ++t) {
        const int j0 = t * KT;
        // Cooperative load of K/V tile: 512 float4 each, 4 per thread
        const float* kbase = qkv + (size_t)(b * Sq + j0) * rs + Dm + h * DHd;
        const float* vbase = kbase + Dm;
#pragma unroll
        for (int i = 0; i < 4; ++i) {
            int v   = tid + i * 128;     // 0..511
            int row = v >> 4;
            int c4  = v & 15;
            Ks[v] = ((const float4*)(kbase + (size_t)row * rs))[c4];
            Vs[v] = ((const float4*)(vbase + (size_t)row * rs))[c4];
        }
        __syncthreads();

        // Scores for 32 keys
        float s[KT];
#pragma unroll
        for (int j = 0; j < KT; ++j) {
            float a = 0.f;
#pragma unroll
            for (int d = 0; d < 16; ++d) {
                float4 k4 = Ks[j * 16 + d];
                a += q[d].x * k4.x + q[d].y * k4.y
                   + q[d].z * k4.z + q[d].w * k4.w;
            }
            s[j] = a * 0.125f;   // 1/sqrt(64)
        }
        if (j0 + KT - 1 > qr0) {   // boundary tiles only
#pragma unroll
            for (int j = 0; j < KT; ++j)
                if (j0 + j > qr) s[j] = -1e30f;
        }

        // Online softmax
        float mt = m;
#pragma unroll
        for (int j = 0; j < KT; ++j) mt = fmaxf(mt, s[j]);
        float alpha = __expf(m - mt);
        l *= alpha;
#pragma unroll
        for (int i = 0; i < 64; ++i) o[i] *= alpha;

#pragma unroll
        for (int j = 0; j < KT; ++j) {
            float p = __expf(s[j] - mt);
            l += p;
#pragma unroll
            for (int d = 0; d < 16; ++d) {
                float4 v4 = Vs[j * 16 + d];
                o[d * 4 + 0] += p * v4.x;
                o[d * 4 + 1] += p * v4.y;
                o[d * 4 + 2] += p * v4.z;
                o[d * 4 + 3] += p * v4.w;
            }
        }
        m = mt;
        __syncthreads();
    }

    const float inv = 1.f / l;
    float4* orow = (float4*)(out + (size_t)(b * Sq + qr) * Dm + h * DHd);
#pragma unroll
    for (int i = 0; i < 16; ++i) {
        float4 ov;
        ov.x = o[i * 4 + 0] * inv;
        ov.y = o[i * 4 + 1] * inv;
        ov.z = o[i * 4 + 2] * inv;
        ov.w = o[i * 4 + 3] * inv;
        orow[i] = ov;
    }
}

// ---------------------------------------------------------------------------
// Launch
// ---------------------------------------------------------------------------
extern "C" void kernel_launch(void* const* d_in, const int* in_sizes, int n_in,
                              void* d_out, int out_size)
{
    const float* x      = (const float*)d_in[0];  // [B,S,D]
    const float* w_attn = (const float*)d_in[1];  // [D,3D]
    const float* b_attn = (const float*)d_in[2];  // [3D]
    const float* w_proj = (const float*)d_in[3];  // [D,D]
    const float* b_proj = (const float*)d_in[4];  // [D]
    float* out = (float*)d_out;

    float* qkv;
    float* attn;
    cudaGetSymbolAddress((void**)&qkv,  g_qkv);
    cudaGetSymbolAddress((void**)&attn, g_attn);

    // 1) QKV projection: [8192,1024] @ [1024,3072] + b
    gemm_bias_kernel<<<dim3(QKVCOLS / TN, Mrows / TM), 256>>>(
        x, w_attn, b_attn, qkv, Mrows, QKVCOLS, Dm);

    // 2) Causal multi-head attention -> merged heads [8192,1024]
    attn_kernel<<<dim3(Sq / QROWS, Hn, Bsz), 128>>>(qkv, attn);

    // 3) Output projection: [8192,1024] @ [1024,1024] + b
    gemm_bias_kernel<<<dim3(Dm / TN, Mrows / TM), 256>>>(
        attn, w_proj, b_proj, out, Mrows, Dm, Dm);
}

// round 3
// speedup vs baseline: 1.3461x; 1.3461x over previous
#include <cuda_runtime.h>
#include <math.h>
#include <stdint.h>

// Problem constants
#define Bsz 4
#define Sq  2048
#define Dm  1024
#define Hn  16
#define DHd 64
#define Mrows (Bsz * Sq)          // 8192
#define QKVCOLS (3 * Dm)          // 3072

// Scratch (allocation-free rule: __device__ globals)
__device__ float g_qkv[(size_t)Mrows * QKVCOLS];   // [8192, 3072] : Q|K|V
__device__ float g_attn[(size_t)Mrows * Dm];       // [8192, 1024] merged heads
__device__ float g_xc [(size_t)Mrows * Dm];        // x rounded to tf32
__device__ float g_wat[(size_t)QKVCOLS * Dm];      // w_attn^T [3072,1024] tf32
__device__ float g_wpt[(size_t)Dm * Dm];           // w_proj^T [1024,1024] tf32

// ---------------------------------------------------------------------------
// tf32 helpers
// ---------------------------------------------------------------------------
__device__ __forceinline__ float tf32r(float x) {
    uint32_t u;
    asm("cvt.rna.tf32.f32 %0, %1;" : "=r"(u) : "f"(x));
    return __uint_as_float(u);
}

__device__ __forceinline__ void mma_tf32(float (&d)[4],
                                         const uint32_t (&a)[4],
                                         const uint32_t (&b)[2]) {
    asm volatile(
        "mma.sync.aligned.m16n8k8.row.col.f32.tf32.tf32.f32 "
        "{%0,%1,%2,%3}, {%4,%5,%6,%7}, {%8,%9}, {%0,%1,%2,%3};"
        : "+f"(d[0]), "+f"(d[1]), "+f"(d[2]), "+f"(d[3])
        : "r"(a[0]), "r"(a[1]), "r"(a[2]), "r"(a[3]), "r"(b[0]), "r"(b[1]));
}

// ---------------------------------------------------------------------------
// Elementwise round-to-tf32 (float4)
// ---------------------------------------------------------------------------
__global__ __launch_bounds__(256)
void cvt_tf32_kernel(const float* __restrict__ in, float* __restrict__ out) {
    int i = blockIdx.x * 256 + threadIdx.x;
    float4 v = ((const float4*)in)[i];
    v.x = tf32r(v.x); v.y = tf32r(v.y); v.z = tf32r(v.z); v.w = tf32r(v.w);
    ((float4*)out)[i] = v;
}

// ---------------------------------------------------------------------------
// Transpose + round-to-tf32: in[R][C] -> out[C][R]
// ---------------------------------------------------------------------------
__global__ __launch_bounds__(256)
void transpose_cvt_kernel(const float* __restrict__ in, float* __restrict__ out,
                          int R, int C) {
    __shared__ float t[32][33];
    const int c0 = blockIdx.x * 32, r0 = blockIdx.y * 32;
    const int tx = threadIdx.x, ty = threadIdx.y;   // 32 x 8
#pragma unroll
    for (int i = 0; i < 32; i += 8)
        t[ty + i][tx] = tf32r(in[(size_t)(r0 + ty + i) * C + c0 + tx]);
    __syncthreads();
#pragma unroll
    for (int i = 0; i < 32; i += 8)
        out[(size_t)(c0 + ty + i) * R + r0 + tx] = t[tx][ty + i];
}

// ---------------------------------------------------------------------------
// tf32 tensor-core GEMM: C[M,N] = A[M,K] @ BT[N,K]^T + bias[N]
// 128x64x32 CTA tile, 256 threads (8 warps, 4m x 2n, 32x32 warp tile).
// K-major SW128-xor-swizzled smem, double buffered (48KB), reg prefetch.
// Inputs must already be tf32-rounded values (bit-exact tf32 in fp32).
// ---------------------------------------------------------------------------
__global__ __launch_bounds__(256)
void gemm_mma_tf32(const float* __restrict__ A, const float* __restrict__ BT,
                   const float* __restrict__ bias, float* __restrict__ C,
                   int M, int N, int K)
{
    __shared__ float4 sA[2][1024];   // 128 rows x 32 k  (swizzled)
    __shared__ float4 sB[2][512];    // 64  rows x 32 k  (swizzled)

    const int tid  = threadIdx.x;
    const int wid  = tid >> 5;
    const int lane = tid & 31;
    const int gid  = lane >> 2;      // 0..7
    const int tig  = lane & 3;       // 0..3
    const int wm   = wid & 3;        // 0..3
    const int wn   = wid >> 2;       // 0..1
    const int m0   = blockIdx.y * 128;
    const int n0   = blockIdx.x * 64;

    // Staging descriptors (constant per thread)
    int aslot[4]; const float* agp[4];
#pragma unroll
    for (int i = 0; i < 4; ++i) {
        int v = tid + i * 256;                // 0..1023
        int row = v >> 3, q = v & 7;
        aslot[i] = row * 8 + (q ^ (row & 7));
        agp[i] = A + (size_t)(m0 + row) * K + q * 4;
    }
    int bslot[2]; const float* bgp[2];
#pragma unroll
    for (int i = 0; i < 2; ++i) {
        int v = tid + i * 256;                // 0..511
        int row = v >> 3, q = v & 7;
        bslot[i] = row * 8 + (q ^ (row & 7));
        bgp[i] = BT + (size_t)(n0 + row) * K + q * 4;
    }

    float acc[2][4][4];
#pragma unroll
    for (int mt = 0; mt < 2; ++mt)
#pragma unroll
        for (int nt = 0; nt < 4; ++nt)
#pragma unroll
            for (int e = 0; e < 4; ++e) acc[mt][nt][e] = 0.f;

    const int nst = K / 32;
    float4 pa[4], pb[2];

    // Prefetch + stage 0
#pragma unroll
    for (int i = 0; i < 4; ++i) pa[i] = *(const float4*)agp[i];
#pragma unroll
    for (int i = 0; i < 2; ++i) pb[i] = *(const float4*)bgp[i];
#pragma unroll
    for (int i = 0; i < 4; ++i) sA[0][aslot[i]] = pa[i];
#pragma unroll
    for (int i = 0; i < 2; ++i) sB[0][bslot[i]] = pb[i];
    __syncthreads();

    for (int s = 0; s < nst; ++s) {
        const int cur = s & 1;
        if (s + 1 < nst) {
            const int ko = (s + 1) * 32;
#pragma unroll
            for (int i = 0; i < 4; ++i) pa[i] = *(const float4*)(agp[i] + ko);
#pragma unroll
            for (int i = 0; i < 2; ++i) pb[i] = *(const float4*)(bgp[i] + ko);
        }

        const float* fA = (const float*)sA[cur];
        const float* fB = (const float*)sB[cur];

#pragma unroll
        for (int kg = 0; kg < 4; ++kg) {
            const int s0 = ((kg * 2) ^ gid) * 4;   // row&7 == gid for all frags
            const int s1 = s0 ^ 4;

            uint32_t af[2][4];
#pragma unroll
            for (int mt = 0; mt < 2; ++mt) {
                int r = wm * 32 + mt * 16 + gid;
                int b0 = r * 32 + tig;
                int b8 = b0 + 8 * 32;
                af[mt][0] = __float_as_uint(fA[b0 + s0]);
                af[mt][1] = __float_as_uint(fA[b8 + s0]);
                af[mt][2] = __float_as_uint(fA[b0 + s1]);
                af[mt][3] = __float_as_uint(fA[b8 + s1]);
            }
            uint32_t bf[4][2];
#pragma unroll
            for (int nt = 0; nt < 4; ++nt) {
                int c = wn * 32 + nt * 8 + gid;
                int b0 = c * 32 + tig;
                bf[nt][0] = __float_as_uint(fB[b0 + s0]);
                bf[nt][1] = __float_as_uint(fB[b0 + s1]);
            }
#pragma unroll
            for (int nt = 0; nt < 4; ++nt)
#pragma unroll
                for (int mt = 0; mt < 2; ++mt)
                    mma_tf32(acc[mt][nt], af[mt], bf[nt]);
        }

        if (s + 1 < nst) {
            const int nxt = cur ^ 1;
#pragma unroll
            for (int i = 0; i < 4; ++i) sA[nxt][aslot[i]] = pa[i];
#pragma unroll
            for (int i = 0; i < 2; ++i) sB[nxt][bslot[i]] = pb[i];
        }
        __syncthreads();
    }

    // Epilogue: + bias, store
#pragma unroll
    for (int mt = 0; mt < 2; ++mt) {
#pragma unroll
        for (int nt = 0; nt < 4; ++nt) {
            int r = m0 + wm * 32 + mt * 16 + gid;
            int c = n0 + wn * 32 + nt * 8 + tig * 2;
            float b0 = bias[c], b1 = bias[c + 1];
            float2 v0 = make_float2(acc[mt][nt][0] + b0, acc[mt][nt][1] + b1);
            float2 v1 = make_float2(acc[mt][nt][2] + b0, acc[mt][nt][3] + b1);
            *(float2*)&C[(size_t)r * N + c] = v0;
            *(float2*)&C[(size_t)(r + 8) * N + c] = v1;
        }
    }
}

// ---------------------------------------------------------------------------
// Flash attention (fp32, causal). One block per (b, h, 128-query-row tile).
// Epilogue rounds output to tf32 so the proj GEMM needs no conversion.
// ---------------------------------------------------------------------------
#define QROWS 128
#define KT    32

__global__ __launch_bounds__(128)
void attn_kernel(const float* __restrict__ qkv, float* __restrict__ out)
{
    __shared__ float4 Ks[KT * 16];
    __shared__ float4 Vs[KT * 16];

    const int tid = threadIdx.x;
    const int h   = blockIdx.y;
    const int b   = blockIdx.z;
    const int qr0 = blockIdx.x * QROWS;
    const int qr  = qr0 + tid;

    const size_t rs = (size_t)QKVCOLS;

    const float4* qrow =
        (const float4*)(qkv + (size_t)(b * Sq + qr) * rs + h * DHd);
    float4 q[16];
#pragma unroll
    for (int i = 0; i < 16; ++i) q[i] = qrow[i];

    float o[64];
#pragma unroll
    for (int i = 0; i < 64; ++i) o[i] = 0.f;
    float m = -1e30f, l = 0.f;

    const int ntiles = (qr0 >> 5) + 4;

    for (int t = 0; t < ntiles; ++t) {
        const int j0 = t * KT;
        const float* kbase = qkv + (size_t)(b * Sq + j0) * rs + Dm + h * DHd;
        const float* vbase = kbase + Dm;
#pragma unroll
        for (int i = 0; i < 4; ++i) {
            int v   = tid + i * 128;
            int row = v >> 4;
            int c4  = v & 15;
            Ks[v] = ((const float4*)(kbase + (size_t)row * rs))[c4];
            Vs[v] = ((const float4*)(vbase + (size_t)row * rs))[c4];
        }
        __syncthreads();

        float s[KT];
#pragma unroll
        for (int j = 0; j < KT; ++j) {
            float a = 0.f;
#pragma unroll
            for (int d = 0; d < 16; ++d) {
                float4 k4 = Ks[j * 16 + d];
                a += q[d].x * k4.x + q[d].y * k4.y
                   + q[d].z * k4.z + q[d].w * k4.w;
            }
            s[j] = a * 0.125f;
        }
        if (j0 + KT - 1 > qr0) {
#pragma unroll
            for (int j = 0; j < KT; ++j)
                if (j0 + j > qr) s[j] = -1e30f;
        }

        float mt = m;
#pragma unroll
        for (int j = 0; j < KT; ++j) mt = fmaxf(mt, s[j]);
        float alpha = __expf(m - mt);
        l *= alpha;
#pragma unroll
        for (int i = 0; i < 64; ++i) o[i] *= alpha;

#pragma unroll
        for (int j = 0; j < KT; ++j) {
            float p = __expf(s[j] - mt);
            l += p;
#pragma unroll
            for (int d = 0; d < 16; ++d) {
                float4 v4 = Vs[j * 16 + d];
                o[d * 4 + 0] += p * v4.x;
                o[d * 4 + 1] += p * v4.y;
                o[d * 4 + 2] += p * v4.z;
                o[d * 4 + 3] += p * v4.w;
            }
        }
        m = mt;
        __syncthreads();
    }

    const float inv = 1.f / l;
    float4* orow = (float4*)(out + (size_t)(b * Sq + qr) * Dm + h * DHd);
#pragma unroll
    for (int i = 0; i < 16; ++i) {
        float4 ov;
        ov.x = tf32r(o[i * 4 + 0] * inv);
        ov.y = tf32r(o[i * 4 + 1] * inv);
        ov.z = tf32r(o[i * 4 + 2] * inv);
        ov.w = tf32r(o[i * 4 + 3] * inv);
        orow[i] = ov;
    }
}

// ---------------------------------------------------------------------------
// Launch
// ---------------------------------------------------------------------------
extern "C" void kernel_launch(void* const* d_in, const int* in_sizes, int n_in,
                              void* d_out, int out_size)
{
    const float* x      = (const float*)d_in[0];  // [B,S,D]
    const float* w_attn = (const float*)d_in[1];  // [D,3D]
    const float* b_attn = (const float*)d_in[2];  // [3D]
    const float* w_proj = (const float*)d_in[3];  // [D,D]
    const float* b_proj = (const float*)d_in[4];  // [D]
    float* out = (float*)d_out;

    float *qkv, *attn, *xc, *wat, *wpt;
    cudaGetSymbolAddress((void**)&qkv,  g_qkv);
    cudaGetSymbolAddress((void**)&attn, g_attn);
    cudaGetSymbolAddress((void**)&xc,   g_xc);
    cudaGetSymbolAddress((void**)&wat,  g_wat);
    cudaGetSymbolAddress((void**)&wpt,  g_wpt);

    // 0) tf32 rounding / weight transposes
    cvt_tf32_kernel<<<(Mrows * Dm) / (4 * 256), 256>>>(x, xc);
    transpose_cvt_kernel<<<dim3(QKVCOLS / 32, Dm / 32), dim3(32, 8)>>>(
        w_attn, wat, Dm, QKVCOLS);
    transpose_cvt_kernel<<<dim3(Dm / 32, Dm / 32), dim3(32, 8)>>>(
        w_proj, wpt, Dm, Dm);

    // 1) QKV projection: [8192,1024] @ [1024,3072] + b  (mma.sync tf32)
    gemm_mma_tf32<<<dim3(QKVCOLS / 64, Mrows / 128), 256>>>(
        xc, wat, b_attn, qkv, Mrows, QKVCOLS, Dm);

    // 2) Causal multi-head attention -> merged heads [8192,1024]
    attn_kernel<<<dim3(Sq / QROWS, Hn, Bsz), 128>>>(qkv, attn);

    // 3) Output projection: [8192,1024] @ [1024,1024] + b  (mma.sync tf32)
    gemm_mma_tf32<<<dim3(Dm / 64, Mrows / 128), 256>>>(
        attn, wpt, b_proj, out, Mrows, Dm, Dm);
}

// round 4
// speedup vs baseline: 3.6598x; 2.7189x over previous
#include <cuda_runtime.h>
#include <math.h>
#include <stdint.h>

// Problem constants
#define Bsz 4
#define Sq  2048
#define Dm  1024
#define Hn  16
#define DHd 64
#define Mrows (Bsz * Sq)          // 8192
#define QKVCOLS (3 * Dm)          // 3072

// Scratch (allocation-free rule: __device__ globals)
__device__ float g_qkv[(size_t)Mrows * QKVCOLS];   // [8192, 3072] : Q|K|V
__device__ float g_attn[(size_t)Mrows * Dm];       // [8192, 1024] merged heads
__device__ float g_xc [(size_t)Mrows * Dm];        // x rounded to tf32
__device__ float g_wat[(size_t)QKVCOLS * Dm];      // w_attn^T [3072,1024] tf32
__device__ float g_wpt[(size_t)Dm * Dm];           // w_proj^T [1024,1024] tf32

// ---------------------------------------------------------------------------
// tf32 helpers
// ---------------------------------------------------------------------------
__device__ __forceinline__ float tf32r(float x) {
    uint32_t u;
    asm("cvt.rna.tf32.f32 %0, %1;" : "=r"(u) : "f"(x));
    return __uint_as_float(u);
}
__device__ __forceinline__ uint32_t tf32u(float x) {
    uint32_t u;
    asm("cvt.rna.tf32.f32 %0, %1;" : "=r"(u) : "f"(x));
    return u;
}

__device__ __forceinline__ void mma_tf32(float (&d)[4],
                                         const uint32_t (&a)[4],
                                         const uint32_t (&b)[2]) {
    asm volatile(
        "mma.sync.aligned.m16n8k8.row.col.f32.tf32.tf32.f32 "
        "{%0,%1,%2,%3}, {%4,%5,%6,%7}, {%8,%9}, {%0,%1,%2,%3};"
        : "+f"(d[0]), "+f"(d[1]), "+f"(d[2]), "+f"(d[3])
        : "r"(a[0]), "r"(a[1]), "r"(a[2]), "r"(a[3]), "r"(b[0]), "r"(b[1]));
}

// ---------------------------------------------------------------------------
// Elementwise round-to-tf32 (float4)
// ---------------------------------------------------------------------------
__global__ __launch_bounds__(256)
void cvt_tf32_kernel(const float* __restrict__ in, float* __restrict__ out) {
    int i = blockIdx.x * 256 + threadIdx.x;
    float4 v = ((const float4*)in)[i];
    v.x = tf32r(v.x); v.y = tf32r(v.y); v.z = tf32r(v.z); v.w = tf32r(v.w);
    ((float4*)out)[i] = v;
}

// ---------------------------------------------------------------------------
// Transpose + round-to-tf32: in[R][C] -> out[C][R]
// ---------------------------------------------------------------------------
__global__ __launch_bounds__(256)
void transpose_cvt_kernel(const float* __restrict__ in, float* __restrict__ out,
                          int R, int C) {
    __shared__ float t[32][33];
    const int c0 = blockIdx.x * 32, r0 = blockIdx.y * 32;
    const int tx = threadIdx.x, ty = threadIdx.y;   // 32 x 8
#pragma unroll
    for (int i = 0; i < 32; i += 8)
        t[ty + i][tx] = tf32r(in[(size_t)(r0 + ty + i) * C + c0 + tx]);
    __syncthreads();
#pragma unroll
    for (int i = 0; i < 32; i += 8)
        out[(size_t)(c0 + ty + i) * R + r0 + tx] = t[tx][ty + i];
}

// ---------------------------------------------------------------------------
// tf32 tensor-core GEMM: C[M,N] = A[M,K] @ BT[N,K]^T + bias[N]
// (unchanged from round 3)
// ---------------------------------------------------------------------------
__global__ __launch_bounds__(256)
void gemm_mma_tf32(const float* __restrict__ A, const float* __restrict__ BT,
                   const float* __restrict__ bias, float* __restrict__ C,
                   int M, int N, int K)
{
    __shared__ float4 sA[2][1024];   // 128 rows x 32 k  (swizzled)
    __shared__ float4 sB[2][512];    // 64  rows x 32 k  (swizzled)

    const int tid  = threadIdx.x;
    const int wid  = tid >> 5;
    const int lane = tid & 31;
    const int gid  = lane >> 2;
    const int tig  = lane & 3;
    const int wm   = wid & 3;
    const int wn   = wid >> 2;
    const int m0   = blockIdx.y * 128;
    const int n0   = blockIdx.x * 64;

    int aslot[4]; const float* agp[4];
#pragma unroll
    for (int i = 0; i < 4; ++i) {
        int v = tid + i * 256;
        int row = v >> 3, q = v & 7;
        aslot[i] = row * 8 + (q ^ (row & 7));
        agp[i] = A + (size_t)(m0 + row) * K + q * 4;
    }
    int bslot[2]; const float* bgp[2];
#pragma unroll
    for (int i = 0; i < 2; ++i) {
        int v = tid + i * 256;
        int row = v >> 3, q = v & 7;
        bslot[i] = row * 8 + (q ^ (row & 7));
        bgp[i] = BT + (size_t)(n0 + row) * K + q * 4;
    }

    float acc[2][4][4];
#pragma unroll
    for (int mt = 0; mt < 2; ++mt)
#pragma unroll
        for (int nt = 0; nt < 4; ++nt)
#pragma unroll
            for (int e = 0; e < 4; ++e) acc[mt][nt][e] = 0.f;

    const int nst = K / 32;
    float4 pa[4], pb[2];

#pragma unroll
    for (int i = 0; i < 4; ++i) pa[i] = *(const float4*)agp[i];
#pragma unroll
    for (int i = 0; i < 2; ++i) pb[i] = *(const float4*)bgp[i];
#pragma unroll
    for (int i = 0; i < 4; ++i) sA[0][aslot[i]] = pa[i];
#pragma unroll
    for (int i = 0; i < 2; ++i) sB[0][bslot[i]] = pb[i];
    __syncthreads();

    for (int s = 0; s < nst; ++s) {
        const int cur = s & 1;
        if (s + 1 < nst) {
            const int ko = (s + 1) * 32;
#pragma unroll
            for (int i = 0; i < 4; ++i) pa[i] = *(const float4*)(agp[i] + ko);
#pragma unroll
            for (int i = 0; i < 2; ++i) pb[i] = *(const float4*)(bgp[i] + ko);
        }

        const float* fA = (const float*)sA[cur];
        const float* fB = (const float*)sB[cur];

#pragma unroll
        for (int kg = 0; kg < 4; ++kg) {
            const int s0 = ((kg * 2) ^ gid) * 4;
            const int s1 = s0 ^ 4;

            uint32_t af[2][4];
#pragma unroll
            for (int mt = 0; mt < 2; ++mt) {
                int r = wm * 32 + mt * 16 + gid;
                int b0 = r * 32 + tig;
                int b8 = b0 + 8 * 32;
                af[mt][0] = __float_as_uint(fA[b0 + s0]);
                af[mt][1] = __float_as_uint(fA[b8 + s0]);
                af[mt][2] = __float_as_uint(fA[b0 + s1]);
                af[mt][3] = __float_as_uint(fA[b8 + s1]);
            }
            uint32_t bf[4][2];
#pragma unroll
            for (int nt = 0; nt < 4; ++nt) {
                int c = wn * 32 + nt * 8 + gid;
                int b0 = c * 32 + tig;
                bf[nt][0] = __float_as_uint(fB[b0 + s0]);
                bf[nt][1] = __float_as_uint(fB[b0 + s1]);
            }
#pragma unroll
            for (int nt = 0; nt < 4; ++nt)
#pragma unroll
                for (int mt = 0; mt < 2; ++mt)
                    mma_tf32(acc[mt][nt], af[mt], bf[nt]);
        }

        if (s + 1 < nst) {
            const int nxt = cur ^ 1;
#pragma unroll
            for (int i = 0; i < 4; ++i) sA[nxt][aslot[i]] = pa[i];
#pragma unroll
            for (int i = 0; i < 2; ++i) sB[nxt][bslot[i]] = pb[i];
        }
        __syncthreads();
    }

#pragma unroll
    for (int mt = 0; mt < 2; ++mt) {
#pragma unroll
        for (int nt = 0; nt < 4; ++nt) {
            int r = m0 + wm * 32 + mt * 16 + gid;
            int c = n0 + wn * 32 + nt * 8 + tig * 2;
            float b0 = bias[c], b1 = bias[c + 1];
            float2 v0 = make_float2(acc[mt][nt][0] + b0, acc[mt][nt][1] + b1);
            float2 v1 = make_float2(acc[mt][nt][2] + b0, acc[mt][nt][3] + b1);
            *(float2*)&C[(size_t)r * N + c] = v0;
            *(float2*)&C[(size_t)(r + 8) * N + c] = v1;
        }
    }
}

// ---------------------------------------------------------------------------
// Flash attention with mma.sync tf32. One CTA = (b, h, 128 q-rows), 4 warps,
// each warp owns 32 q rows. KV processed in 64-key tiles:
//   K tile in smem [64 key][68 pad]   (B-frags for QK^T, conflict-free)
//   V tile transposed [64 dh][72 pad] (B-frags for P@V as float2)
// P (post-softmax) feeds the PV mma by pure register renaming via a key
// permutation absorbed into Vt indexing (sum over keys is order-invariant).
// ---------------------------------------------------------------------------
__global__ __launch_bounds__(128, 2)
void attn_mma_kernel(const float* __restrict__ qkv, float* __restrict__ out)
{
    __shared__ __align__(16) float sm[64 * 68 + 64 * 72];  // 35840 B
    float* sK  = sm;             // [64][68]
    float* sVt = sm + 64 * 68;   // [64][72]

    const int tid  = threadIdx.x;
    const int wid  = tid >> 5;
    const int lane = tid & 31;
    const int gid  = lane >> 2;
    const int tig  = lane & 3;
    const int h    = blockIdx.y;
    const int b    = blockIdx.z;
    const int qr0  = blockIdx.x * 128;

    const size_t rs = (size_t)QKVCOLS;
    const float* qbase = qkv + (size_t)(b * Sq + qr0) * rs + h * DHd;

    // --- stage Q [128][64] into smem (stride 68), then load frags ---
#pragma unroll
    for (int i = 0; i < 16; ++i) {
        int v = tid + i * 128;
        int row = v >> 4, c4 = v & 15;
        float4 q4 = *(const float4*)(qbase + (size_t)row * rs + c4 * 4);
        *(float4*)(sm + row * 68 + c4 * 4) = q4;
    }
    __syncthreads();

    uint32_t qa[2][8][4];
#pragma unroll
    for (int mt = 0; mt < 2; ++mt) {
        const int r0 = wid * 32 + mt * 16 + gid;
#pragma unroll
        for (int kt = 0; kt < 8; ++kt) {
            const int c = kt * 8 + tig;
            qa[mt][kt][0] = tf32u(sm[r0 * 68 + c] * 0.125f);
            qa[mt][kt][1] = tf32u(sm[(r0 + 8) * 68 + c] * 0.125f);
            qa[mt][kt][2] = tf32u(sm[r0 * 68 + c + 4] * 0.125f);
            qa[mt][kt][3] = tf32u(sm[(r0 + 8) * 68 + c + 4] * 0.125f);
        }
    }
    __syncthreads();

    float oacc[2][8][4];
#pragma unroll
    for (int mt = 0; mt < 2; ++mt)
#pragma unroll
        for (int dt = 0; dt < 8; ++dt)
#pragma unroll
            for (int e = 0; e < 4; ++e) oacc[mt][dt][e] = 0.f;
    float mrow[2][2] = {{-1e30f, -1e30f}, {-1e30f, -1e30f}};
    float lrow[2][2] = {{0.f, 0.f}, {0.f, 0.f}};

    const int ntiles = qr0 / 64 + 2;

    for (int t = 0; t < ntiles; ++t) {
        const int j0 = t * 64;
        const float* kb = qkv + (size_t)(b * Sq + j0) * rs + Dm + h * DHd;
        const float* vb = kb + Dm;

        // stage K (row-major, rounded) and V^T (rounded)
#pragma unroll
        for (int i = 0; i < 8; ++i) {
            int v = tid + i * 128;
            int row = v >> 4, c4 = v & 15;
            float4 k4 = *(const float4*)(kb + (size_t)row * rs + c4 * 4);
            k4.x = tf32r(k4.x); k4.y = tf32r(k4.y);
            k4.z = tf32r(k4.z); k4.w = tf32r(k4.w);
            *(float4*)(sK + row * 68 + c4 * 4) = k4;
            float4 v4 = *(const float4*)(vb + (size_t)row * rs + c4 * 4);
            sVt[(c4 * 4 + 0) * 72 + row] = tf32r(v4.x);
            sVt[(c4 * 4 + 1) * 72 + row] = tf32r(v4.y);
            sVt[(c4 * 4 + 2) * 72 + row] = tf32r(v4.z);
            sVt[(c4 * 4 + 3) * 72 + row] = tf32r(v4.w);
        }
        __syncthreads();

        // --- S = Q @ K^T (scaled) ---
        float sacc[2][8][4];
#pragma unroll
        for (int mt = 0; mt < 2; ++mt)
#pragma unroll
            for (int nt = 0; nt < 8; ++nt)
#pragma unroll
                for (int e = 0; e < 4; ++e) sacc[mt][nt][e] = 0.f;

#pragma unroll
        for (int nt = 0; nt < 8; ++nt) {
            const int krow = (nt * 8 + gid) * 68;
#pragma unroll
            for (int kt = 0; kt < 8; ++kt) {
                uint32_t kf[2];
                kf[0] = __float_as_uint(sK[krow + kt * 8 + tig]);
                kf[1] = __float_as_uint(sK[krow + kt * 8 + tig + 4]);
                mma_tf32(sacc[0][nt], qa[0][kt], kf);
                mma_tf32(sacc[1][nt], qa[1][kt], kf);
            }
        }

        // --- causal mask (boundary tiles only) ---
        if (j0 + 63 > qr0) {
#pragma unroll
            for (int mt = 0; mt < 2; ++mt) {
                const int r0 = qr0 + wid * 32 + mt * 16 + gid;
#pragma unroll
                for (int nt = 0; nt < 8; ++nt) {
                    const int c = j0 + nt * 8 + 2 * tig;
                    if (c > r0)         sacc[mt][nt][0] = -1e30f;
                    if (c + 1 > r0)     sacc[mt][nt][1] = -1e30f;
                    if (c > r0 + 8)     sacc[mt][nt][2] = -1e30f;
                    if (c + 1 > r0 + 8) sacc[mt][nt][3] = -1e30f;
                }
            }
        }

        // --- online softmax (per row-slot), P left in sacc ---
#pragma unroll
        for (int mt = 0; mt < 2; ++mt) {
#pragma unroll
            for (int hf = 0; hf < 2; ++hf) {
                float mx = mrow[mt][hf];
#pragma unroll
                for (int nt = 0; nt < 8; ++nt)
                    mx = fmaxf(mx, fmaxf(sacc[mt][nt][hf * 2],
                                         sacc[mt][nt][hf * 2 + 1]));
                mx = fmaxf(mx, __shfl_xor_sync(0xffffffffu, mx, 1));
                mx = fmaxf(mx, __shfl_xor_sync(0xffffffffu, mx, 2));
                const float alpha = __expf(mrow[mt][hf] - mx);
                mrow[mt][hf] = mx;
                float lsum = lrow[mt][hf] * alpha;
#pragma unroll
                for (int nt = 0; nt < 8; ++nt) {
                    float p0 = __expf(sacc[mt][nt][hf * 2] - mx);
                    float p1 = __expf(sacc[mt][nt][hf * 2 + 1] - mx);
                    sacc[mt][nt][hf * 2] = p0;
                    sacc[mt][nt][hf * 2 + 1] = p1;
                    lsum += p0 + p1;
                }
                lrow[mt][hf] = lsum;
#pragma unroll
                for (int dt = 0; dt < 8; ++dt) {
                    oacc[mt][dt][hf * 2]     *= alpha;
                    oacc[mt][dt][hf * 2 + 1] *= alpha;
                }
            }
        }

        // --- O += P @ V  (P renamed to A-frags; key perm absorbed in Vt) ---
#pragma unroll
        for (int dt = 0; dt < 8; ++dt) {
            const int vrow = (dt * 8 + gid) * 72;
#pragma unroll
            for (int kt = 0; kt < 8; ++kt) {
                float2 vv = *(const float2*)(sVt + vrow + kt * 8 + 2 * tig);
                uint32_t vf[2] = {__float_as_uint(vv.x), __float_as_uint(vv.y)};
#pragma unroll
                for (int mt = 0; mt < 2; ++mt) {
                    uint32_t pf[4] = {__float_as_uint(sacc[mt][kt][0]),
                                      __float_as_uint(sacc[mt][kt][2]),
                                      __float_as_uint(sacc[mt][kt][1]),
                                      __float_as_uint(sacc[mt][kt][3])};
                    mma_tf32(oacc[mt][dt], pf, vf);
                }
            }
        }
        __syncthreads();
    }

    // --- epilogue: reduce l across tig group, normalize, store (tf32) ---
#pragma unroll
    for (int mt = 0; mt < 2; ++mt)
#pragma unroll
        for (int hf = 0; hf < 2; ++hf) {
            float l = lrow[mt][hf];
            l += __shfl_xor_sync(0xffffffffu, l, 1);
            l += __shfl_xor_sync(0xffffffffu, l, 2);
            lrow[mt][hf] = 1.f / l;
        }

    float* ob = out + (size_t)(b * Sq + qr0) * Dm + h * DHd;
#pragma unroll
    for (int mt = 0; mt < 2; ++mt) {
        const int r0 = wid * 32 + mt * 16 + gid;
#pragma unroll
        for (int dt = 0; dt < 8; ++dt) {
            const int c = dt * 8 + 2 * tig;
            float2 w0, w1;
            w0.x = tf32r(oacc[mt][dt][0] * lrow[mt][0]);
            w0.y = tf32r(oacc[mt][dt][1] * lrow[mt][0]);
            w1.x = tf32r(oacc[mt][dt][2] * lrow[mt][1]);
            w1.y = tf32r(oacc[mt][dt][3] * lrow[mt][1]);
            *(float2*)(ob + (size_t)r0 * Dm + c) = w0;
            *(float2*)(ob + (size_t)(r0 + 8) * Dm + c) = w1;
        }
    }
}

// ---------------------------------------------------------------------------
// Launch
// ---------------------------------------------------------------------------
extern "C" void kernel_launch(void* const* d_in, const int* in_sizes, int n_in,
                              void* d_out, int out_size)
{
    const float* x      = (const float*)d_in[0];  // [B,S,D]
    const float* w_attn = (const float*)d_in[1];  // [D,3D]
    const float* b_attn = (const float*)d_in[2];  // [3D]
    const float* w_proj = (const float*)d_in[3];  // [D,D]
    const float* b_proj = (const float*)d_in[4];  // [D]
    float* out = (float*)d_out;

    float *qkv, *attn, *xc, *wat, *wpt;
    cudaGetSymbolAddress((void**)&qkv,  g_qkv);
    cudaGetSymbolAddress((void**)&attn, g_attn);
    cudaGetSymbolAddress((void**)&xc,   g_xc);
    cudaGetSymbolAddress((void**)&wat,  g_wat);
    cudaGetSymbolAddress((void**)&wpt,  g_wpt);

    // 0) tf32 rounding / weight transposes
    cvt_tf32_kernel<<<(Mrows * Dm) / (4 * 256), 256>>>(x, xc);
    transpose_cvt_kernel<<<dim3(QKVCOLS / 32, Dm / 32), dim3(32, 8)>>>(
        w_attn, wat, Dm, QKVCOLS);
    transpose_cvt_kernel<<<dim3(Dm / 32, Dm / 32), dim3(32, 8)>>>(
        w_proj, wpt, Dm, Dm);

    // 1) QKV projection (mma.sync tf32)
    gemm_mma_tf32<<<dim3(QKVCOLS / 64, Mrows / 128), 256>>>(
        xc, wat, b_attn, qkv, Mrows, QKVCOLS, Dm);

    // 2) Causal multi-head attention (mma.sync tf32 flash)
    attn_mma_kernel<<<dim3(Sq / 128, Hn, Bsz), 128>>>(qkv, attn);

    // 3) Output projection (mma.sync tf32)
    gemm_mma_tf32<<<dim3(Dm / 64, Mrows / 128), 256>>>(
        attn, wpt, b_proj, out, Mrows, Dm, Dm);
}

// round 5
// speedup vs baseline: 4.4349x; 1.2118x over previous
#include <cuda_runtime.h>
#include <math.h>
#include <stdint.h>

// Problem constants
#define Bsz 4
#define Sq  2048
#define Dm  1024
#define Hn  16
#define DHd 64
#define Mrows (Bsz * Sq)          // 8192
#define QKVCOLS (3 * Dm)          // 3072

// Scratch (allocation-free rule: __device__ globals)
__device__ float g_qkv[(size_t)Mrows * QKVCOLS];   // [8192, 3072] : Q|K|V
__device__ float g_attn[(size_t)Mrows * Dm];       // [8192, 1024] merged heads
__device__ float g_xc [(size_t)Mrows * Dm];        // x rounded to tf32
__device__ float g_wat[(size_t)QKVCOLS * Dm];      // w_attn^T [3072,1024] tf32
__device__ float g_wpt[(size_t)Dm * Dm];           // w_proj^T [1024,1024] tf32

// ---------------------------------------------------------------------------
// tf32 helpers
// ---------------------------------------------------------------------------
__device__ __forceinline__ float tf32r(float x) {
    uint32_t u;
    asm("cvt.rna.tf32.f32 %0, %1;" : "=r"(u) : "f"(x));
    return __uint_as_float(u);
}
__device__ __forceinline__ uint32_t tf32u(float x) {
    uint32_t u;
    asm("cvt.rna.tf32.f32 %0, %1;" : "=r"(u) : "f"(x));
    return u;
}

__device__ __forceinline__ void mma_tf32(float (&d)[4],
                                         const uint32_t (&a)[4],
                                         const uint32_t (&b)[2]) {
    asm volatile(
        "mma.sync.aligned.m16n8k8.row.col.f32.tf32.tf32.f32 "
        "{%0,%1,%2,%3}, {%4,%5,%6,%7}, {%8,%9}, {%0,%1,%2,%3};"
        : "+f"(d[0]), "+f"(d[1]), "+f"(d[2]), "+f"(d[3])
        : "r"(a[0]), "r"(a[1]), "r"(a[2]), "r"(a[3]), "r"(b[0]), "r"(b[1]));
}

// ---------------------------------------------------------------------------
// Elementwise round-to-tf32 (float4)
// ---------------------------------------------------------------------------
__global__ __launch_bounds__(256)
void cvt_tf32_kernel(const float* __restrict__ in, float* __restrict__ out) {
    int i = blockIdx.x * 256 + threadIdx.x;
    float4 v = ((const float4*)in)[i];
    v.x = tf32r(v.x); v.y = tf32r(v.y); v.z = tf32r(v.z); v.w = tf32r(v.w);
    ((float4*)out)[i] = v;
}

// ---------------------------------------------------------------------------
// Transpose + round-to-tf32: in[R][C] -> out[C][R]
// ---------------------------------------------------------------------------
__global__ __launch_bounds__(256)
void transpose_cvt_kernel(const float* __restrict__ in, float* __restrict__ out,
                          int R, int C) {
    __shared__ float t[32][33];
    const int c0 = blockIdx.x * 32, r0 = blockIdx.y * 32;
    const int tx = threadIdx.x, ty = threadIdx.y;   // 32 x 8
#pragma unroll
    for (int i = 0; i < 32; i += 8)
        t[ty + i][tx] = tf32r(in[(size_t)(r0 + ty + i) * C + c0 + tx]);
    __syncthreads();
#pragma unroll
    for (int i = 0; i < 32; i += 8)
        out[(size_t)(c0 + ty + i) * R + r0 + tx] = t[tx][ty + i];
}

// ---------------------------------------------------------------------------
// tf32 GEMM v2: C[M,N] = A[M,K] @ BT[N,K]^T + bias[N]
// CTA tile 128x128, 4 warps (2x2), warp tile 64x64 -> 16 FLOP/byte of LDS.
// K staged 16 wide, double buffered (32KB smem), register prefetch.
// Smem layout per row (16 floats): float4 quad q stored at q ^ ((row>>1)&3).
// Bank-verified conflict-free for both STS.128 staging and fragment LDS.
// ---------------------------------------------------------------------------
__global__ __launch_bounds__(128)
void gemm_mma_tf32(const float* __restrict__ A, const float* __restrict__ BT,
                   const float* __restrict__ bias, float* __restrict__ C,
                   int M, int N, int K)
{
    __shared__ float sA[2][128 * 16];   // 8KB per stage
    __shared__ float sB[2][128 * 16];

    const int tid  = threadIdx.x;
    const int wid  = tid >> 5;
    const int lane = tid & 31;
    const int gid  = lane >> 2;
    const int tig  = lane & 3;
    const int wm   = wid & 1;
    const int wn   = wid >> 1;
    const int m0   = blockIdx.y * 128;
    const int n0   = blockIdx.x * 128;

    // Staging: thread handles rows (tid>>2)+32i, quad q=tid&3, i=0..3
    const int srow = tid >> 2;
    const int sq   = tid & 3;
    const int slot0 = srow * 16 + ((sq ^ ((srow >> 1) & 3)) << 2);
    const float* aP = A  + (size_t)(m0 + srow) * K + sq * 4;
    const float* bP = BT + (size_t)(n0 + srow) * K + sq * 4;
    const size_t rstep = (size_t)32 * K;

    float acc[4][8][4];
#pragma unroll
    for (int mt = 0; mt < 4; ++mt)
#pragma unroll
        for (int nt = 0; nt < 8; ++nt)
#pragma unroll
            for (int e = 0; e < 4; ++e) acc[mt][nt][e] = 0.f;

    const int nst = K / 16;
    float4 pa[4], pb[4];

    // Prefetch + stage 0
#pragma unroll
    for (int i = 0; i < 4; ++i) pa[i] = *(const float4*)(aP + i * rstep);
#pragma unroll
    for (int i = 0; i < 4; ++i) pb[i] = *(const float4*)(bP + i * rstep);
#pragma unroll
    for (int i = 0; i < 4; ++i) *(float4*)&sA[0][slot0 + 512 * i] = pa[i];
#pragma unroll
    for (int i = 0; i < 4; ++i) *(float4*)&sB[0][slot0 + 512 * i] = pb[i];
    __syncthreads();

    const int xa = ((wm * 64 + gid) >> 1) & 3;   // row-swizzle key (A frags)
    const int xb = ((wn * 64 + gid) >> 1) & 3;   // col-swizzle key (B frags)

    for (int s = 0; s < nst; ++s) {
        const int cur = s & 1;
        if (s + 1 < nst) {
            const int ko = (s + 1) * 16;
#pragma unroll
            for (int i = 0; i < 4; ++i) pa[i] = *(const float4*)(aP + i * rstep + ko);
#pragma unroll
            for (int i = 0; i < 4; ++i) pb[i] = *(const float4*)(bP + i * rstep + ko);
        }

        const float* fA = sA[cur];
        const float* fB = sB[cur];

#pragma unroll
        for (int kt = 0; kt < 2; ++kt) {
            uint32_t af[4][4];
#pragma unroll
            for (int mt = 0; mt < 4; ++mt) {
                const int r = wm * 64 + mt * 16 + gid;
                const int base = r * 16;
                const int w0 = base + (((2 * kt)     ^ xa) << 2) + tig;
                const int w1 = base + (((2 * kt + 1) ^ xa) << 2) + tig;
                af[mt][0] = __float_as_uint(fA[w0]);
                af[mt][1] = __float_as_uint(fA[w0 + 128]);
                af[mt][2] = __float_as_uint(fA[w1]);
                af[mt][3] = __float_as_uint(fA[w1 + 128]);
            }
#pragma unroll
            for (int nt = 0; nt < 8; ++nt) {
                const int c = wn * 64 + nt * 8 + gid;
                const int base = c * 16;
                uint32_t bf[2];
                bf[0] = __float_as_uint(fB[base + (((2 * kt)     ^ xb) << 2) + tig]);
                bf[1] = __float_as_uint(fB[base + (((2 * kt + 1) ^ xb) << 2) + tig]);
#pragma unroll
                for (int mt = 0; mt < 4; ++mt)
                    mma_tf32(acc[mt][nt], af[mt], bf);
            }
        }

        if (s + 1 < nst) {
            const int nxt = cur ^ 1;
#pragma unroll
            for (int i = 0; i < 4; ++i) *(float4*)&sA[nxt][slot0 + 512 * i] = pa[i];
#pragma unroll
            for (int i = 0; i < 4; ++i) *(float4*)&sB[nxt][slot0 + 512 * i] = pb[i];
        }
        __syncthreads();
    }

    // Epilogue: + bias, store
#pragma unroll
    for (int mt = 0; mt < 4; ++mt) {
        const int r = m0 + wm * 64 + mt * 16 + gid;
#pragma unroll
        for (int nt = 0; nt < 8; ++nt) {
            const int c = n0 + wn * 64 + nt * 8 + tig * 2;
            float b0 = bias[c], b1 = bias[c + 1];
            float2 v0 = make_float2(acc[mt][nt][0] + b0, acc[mt][nt][1] + b1);
            float2 v1 = make_float2(acc[mt][nt][2] + b0, acc[mt][nt][3] + b1);
            *(float2*)&C[(size_t)r * N + c] = v0;
            *(float2*)&C[(size_t)(r + 8) * N + c] = v1;
        }
    }
}

// ---------------------------------------------------------------------------
// Flash attention with mma.sync tf32. One CTA = (b, h, 128 q-rows), 4 warps.
// V-transpose staging re-mapped so STS banks = key-row (conflict-free);
// previously 16-way conflicted (288*c4 == 0 mod 32).
// ---------------------------------------------------------------------------
__global__ __launch_bounds__(128, 2)
void attn_mma_kernel(const float* __restrict__ qkv, float* __restrict__ out)
{
    __shared__ __align__(16) float sm[64 * 68 + 64 * 72];  // 35840 B
    float* sK  = sm;             // [64 key][68]
    float* sVt = sm + 64 * 68;   // [64 dh][72]

    const int tid  = threadIdx.x;
    const int wid  = tid >> 5;
    const int lane = tid & 31;
    const int gid  = lane >> 2;
    const int tig  = lane & 3;
    const int h    = blockIdx.y;
    const int b    = blockIdx.z;
    const int qr0  = blockIdx.x * 128;

    const size_t rs = (size_t)QKVCOLS;
    const float* qbase = qkv + (size_t)(b * Sq + qr0) * rs + h * DHd;

    // --- stage Q [128][64] into smem (stride 68), then load frags ---
#pragma unroll
    for (int i = 0; i < 16; ++i) {
        int v = tid + i * 128;
        int row = v >> 4, c4 = v & 15;
        float4 q4 = *(const float4*)(qbase + (size_t)row * rs + c4 * 4);
        *(float4*)(sm + row * 68 + c4 * 4) = q4;
    }
    __syncthreads();

    uint32_t qa[2][8][4];
#pragma unroll
    for (int mt = 0; mt < 2; ++mt) {
        const int r0 = wid * 32 + mt * 16 + gid;
#pragma unroll
        for (int kt = 0; kt < 8; ++kt) {
            const int c = kt * 8 + tig;
            qa[mt][kt][0] = tf32u(sm[r0 * 68 + c] * 0.125f);
            qa[mt][kt][1] = tf32u(sm[(r0 + 8) * 68 + c] * 0.125f);
            qa[mt][kt][2] = tf32u(sm[r0 * 68 + c + 4] * 0.125f);
            qa[mt][kt][3] = tf32u(sm[(r0 + 8) * 68 + c + 4] * 0.125f);
        }
    }
    __syncthreads();

    float oacc[2][8][4];
#pragma unroll
    for (int mt = 0; mt < 2; ++mt)
#pragma unroll
        for (int dt = 0; dt < 8; ++dt)
#pragma unroll
            for (int e = 0; e < 4; ++e) oacc[mt][dt][e] = 0.f;
    float mrow[2][2] = {{-1e30f, -1e30f}, {-1e30f, -1e30f}};
    float lrow[2][2] = {{0.f, 0.f}, {0.f, 0.f}};

    const int ntiles = qr0 / 64 + 2;
    const int rv = tid & 63;          // V staging: this thread's key row
    const int ch = (tid >> 6) * 8;    // and its 8 dh-quads

    for (int t = 0; t < ntiles; ++t) {
        const int j0 = t * 64;
        const float* kb = qkv + (size_t)(b * Sq + j0) * rs + Dm + h * DHd;
        const float* vb = kb + Dm;

        // stage K rows (row-major, rounded) — STS.128, conflict-free
#pragma unroll
        for (int i = 0; i < 8; ++i) {
            int v = tid + i * 128;
            int row = v >> 4, c4 = v & 15;
            float4 k4 = *(const float4*)(kb + (size_t)row * rs + c4 * 4);
            k4.x = tf32r(k4.x); k4.y = tf32r(k4.y);
            k4.z = tf32r(k4.z); k4.w = tf32r(k4.w);
            *(float4*)(sK + row * 68 + c4 * 4) = k4;
        }
        // stage V^T: lane varies key-row -> scalar STS banks all distinct
        const float* vrow = vb + (size_t)rv * rs + ch * 4;
#pragma unroll
        for (int j = 0; j < 8; ++j) {
            const int c4 = ch + j;
            float4 v4 = *(const float4*)(vrow + j * 4);
            sVt[(c4 * 4 + 0) * 72 + rv] = tf32r(v4.x);
            sVt[(c4 * 4 + 1) * 72 + rv] = tf32r(v4.y);
            sVt[(c4 * 4 + 2) * 72 + rv] = tf32r(v4.z);
            sVt[(c4 * 4 + 3) * 72 + rv] = tf32r(v4.w);
        }
        __syncthreads();

        // --- S = Q @ K^T (scaled) ---
        float sacc[2][8][4];
#pragma unroll
        for (int mt = 0; mt < 2; ++mt)
#pragma unroll
            for (int nt = 0; nt < 8; ++nt)
#pragma unroll
                for (int e = 0; e < 4; ++e) sacc[mt][nt][e] = 0.f;

#pragma unroll
        for (int nt = 0; nt < 8; ++nt) {
            const int krow = (nt * 8 + gid) * 68;
#pragma unroll
            for (int kt = 0; kt < 8; ++kt) {
                uint32_t kf[2];
                kf[0] = __float_as_uint(sK[krow + kt * 8 + tig]);
                kf[1] = __float_as_uint(sK[krow + kt * 8 + tig + 4]);
                mma_tf32(sacc[0][nt], qa[0][kt], kf);
                mma_tf32(sacc[1][nt], qa[1][kt], kf);
            }
        }

        // --- causal mask (boundary tiles only) ---
        if (j0 + 63 > qr0) {
#pragma unroll
            for (int mt = 0; mt < 2; ++mt) {
                const int r0 = qr0 + wid * 32 + mt * 16 + gid;
#pragma unroll
                for (int nt = 0; nt < 8; ++nt) {
                    const int c = j0 + nt * 8 + 2 * tig;
                    if (c > r0)         sacc[mt][nt][0] = -1e30f;
                    if (c + 1 > r0)     sacc[mt][nt][1] = -1e30f;
                    if (c > r0 + 8)     sacc[mt][nt][2] = -1e30f;
                    if (c + 1 > r0 + 8) sacc[mt][nt][3] = -1e30f;
                }
            }
        }

        // --- online softmax (per row-slot), P left in sacc ---
#pragma unroll
        for (int mt = 0; mt < 2; ++mt) {
#pragma unroll
            for (int hf = 0; hf < 2; ++hf) {
                float mx = mrow[mt][hf];
#pragma unroll
                for (int nt = 0; nt < 8; ++nt)
                    mx = fmaxf(mx, fmaxf(sacc[mt][nt][hf * 2],
                                         sacc[mt][nt][hf * 2 + 1]));
                mx = fmaxf(mx, __shfl_xor_sync(0xffffffffu, mx, 1));
                mx = fmaxf(mx, __shfl_xor_sync(0xffffffffu, mx, 2));
                const float alpha = __expf(mrow[mt][hf] - mx);
                mrow[mt][hf] = mx;
                float lsum = lrow[mt][hf] * alpha;
#pragma unroll
                for (int nt = 0; nt < 8; ++nt) {
                    float p0 = __expf(sacc[mt][nt][hf * 2] - mx);
                    float p1 = __expf(sacc[mt][nt][hf * 2 + 1] - mx);
                    sacc[mt][nt][hf * 2] = p0;
                    sacc[mt][nt][hf * 2 + 1] = p1;
                    lsum += p0 + p1;
                }
                lrow[mt][hf] = lsum;
#pragma unroll
                for (int dt = 0; dt < 8; ++dt) {
                    oacc[mt][dt][hf * 2]     *= alpha;
                    oacc[mt][dt][hf * 2 + 1] *= alpha;
                }
            }
        }

        // --- O += P @ V  (P renamed to A-frags; key perm absorbed in Vt) ---
#pragma unroll
        for (int dt = 0; dt < 8; ++dt) {
            const int vrow2 = (dt * 8 + gid) * 72;
#pragma unroll
            for (int kt = 0; kt < 8; ++kt) {
                float2 vv = *(const float2*)(sVt + vrow2 + kt * 8 + 2 * tig);
                uint32_t vf[2] = {__float_as_uint(vv.x), __float_as_uint(vv.y)};
#pragma unroll
                for (int mt = 0; mt < 2; ++mt) {
                    uint32_t pf[4] = {__float_as_uint(sacc[mt][kt][0]),
                                      __float_as_uint(sacc[mt][kt][2]),
                                      __float_as_uint(sacc[mt][kt][1]),
                                      __float_as_uint(sacc[mt][kt][3])};
                    mma_tf32(oacc[mt][dt], pf, vf);
                }
            }
        }
        __syncthreads();
    }

    // --- epilogue: reduce l across tig group, normalize, store (tf32) ---
#pragma unroll
    for (int mt = 0; mt < 2; ++mt)
#pragma unroll
        for (int hf = 0; hf < 2; ++hf) {
            float l = lrow[mt][hf];
            l += __shfl_xor_sync(0xffffffffu, l, 1);
            l += __shfl_xor_sync(0xffffffffu, l, 2);
            lrow[mt][hf] = 1.f / l;
        }

    float* ob = out + (size_t)(b * Sq + qr0) * Dm + h * DHd;
#pragma unroll
    for (int mt = 0; mt < 2; ++mt) {
        const int r0 = wid * 32 + mt * 16 + gid;
#pragma unroll
        for (int dt = 0; dt < 8; ++dt) {
            const int c = dt * 8 + 2 * tig;
            float2 w0, w1;
            w0.x = tf32r(oacc[mt][dt][0] * lrow[mt][0]);
            w0.y = tf32r(oacc[mt][dt][1] * lrow[mt][0]);
            w1.x = tf32r(oacc[mt][dt][2] * lrow[mt][1]);
            w1.y = tf32r(oacc[mt][dt][3] * lrow[mt][1]);
            *(float2*)(ob + (size_t)r0 * Dm + c) = w0;
            *(float2*)(ob + (size_t)(r0 + 8) * Dm + c) = w1;
        }
    }
}

// ---------------------------------------------------------------------------
// Launch
// ---------------------------------------------------------------------------
extern "C" void kernel_launch(void* const* d_in, const int* in_sizes, int n_in,
                              void* d_out, int out_size)
{
    const float* x      = (const float*)d_in[0];  // [B,S,D]
    const float* w_attn = (const float*)d_in[1];  // [D,3D]
    const float* b_attn = (const float*)d_in[2];  // [3D]
    const float* w_proj = (const float*)d_in[3];  // [D,D]
    const float* b_proj = (const float*)d_in[4];  // [D]
    float* out = (float*)d_out;

    float *qkv, *attn, *xc, *wat, *wpt;
    cudaGetSymbolAddress((void**)&qkv,  g_qkv);
    cudaGetSymbolAddress((void**)&attn, g_attn);
    cudaGetSymbolAddress((void**)&xc,   g_xc);
    cudaGetSymbolAddress((void**)&wat,  g_wat);
    cudaGetSymbolAddress((void**)&wpt,  g_wpt);

    // 0) tf32 rounding / weight transposes
    cvt_tf32_kernel<<<(Mrows * Dm) / (4 * 256), 256>>>(x, xc);
    transpose_cvt_kernel<<<dim3(QKVCOLS / 32, Dm / 32), dim3(32, 8)>>>(
        w_attn, wat, Dm, QKVCOLS);
    transpose_cvt_kernel<<<dim3(Dm / 32, Dm / 32), dim3(32, 8)>>>(
        w_proj, wpt, Dm, Dm);

    // 1) QKV projection (mma.sync tf32, 64x64 warp tile)
    gemm_mma_tf32<<<dim3(QKVCOLS / 128, Mrows / 128), 128>>>(
        xc, wat, b_attn, qkv, Mrows, QKVCOLS, Dm);

    // 2) Causal multi-head attention (mma.sync tf32 flash)
    attn_mma_kernel<<<dim3(Sq / 128, Hn, Bsz), 128>>>(qkv, attn);

    // 3) Output projection (mma.sync tf32, 64x64 warp tile)
    gemm_mma_tf32<<<dim3(Dm / 128, Mrows / 128), 128>>>(
        attn, wpt, b_proj, out, Mrows, Dm, Dm);
}